// round 1
// baseline (speedup 1.0000x reference)
#include <cuda_runtime.h>
#include <cstdint>

#define S_LEN 2048
#define DM    1024
#define NH    16
#define HD    64
#define BATCH 2
#define M_TOT (BATCH * S_LEN)   // 4096

// ---------------- scratch (device globals: no allocation allowed) ----------
__device__ float g_Q[M_TOT * DM];
__device__ float g_K[M_TOT * DM];
__device__ float g_V[M_TOT * DM];
__device__ float g_O[M_TOT * DM];
__device__ float g_pad[BATCH * S_LEN];   // 1.0f = padded (id==0), 0.0f = valid

// ---------------------------------------------------------------------------
// Pad-flag kernel with int32/int64 dtype sniffing.
// If input_ids is int64, the odd 32-bit words of the first 2048 elements are
// all high-halves of values in [0,32000) -> all zero. If int32, those words
// are random ids -> almost surely nonzero. Deterministic for fixed inputs.
// ---------------------------------------------------------------------------
__global__ void pad_kernel(const int* __restrict__ ids)
{
    __shared__ int orv;
    if (threadIdx.x == 0) orv = 0;
    __syncthreads();
    int local = 0;
    for (int i = threadIdx.x; i < 2048; i += blockDim.x)
        local |= ids[2 * i + 1];          // index <= 4095: in-bounds either way
    atomicOr(&orv, local);
    __syncthreads();
    bool is64 = (orv == 0);
    for (int i = threadIdx.x; i < BATCH * S_LEN; i += blockDim.x) {
        int nz = is64 ? ((ids[2 * i] | ids[2 * i + 1]) != 0) : (ids[i] != 0);
        g_pad[i] = nz ? 0.0f : 1.0f;
    }
}

// ---------------------------------------------------------------------------
// SGEMM (NT): C[m][n] = sum_k A[m][k] * W[n][k] + bias[n]
// 128x128 block tile, BK=8, 256 threads, 8x8 per thread.
// M,N,K all multiples of 128 here -> no bounds checks.
// ---------------------------------------------------------------------------
__global__ __launch_bounds__(256, 2)
void sgemm_tn(const float* __restrict__ A, const float* __restrict__ W,
              const float* __restrict__ bias, float* __restrict__ C,
              int M, int N, int K)
{
    __shared__ float As[8][128];
    __shared__ float Bs[8][128];

    const int tid  = threadIdx.x;
    const int row0 = blockIdx.y * 128;
    const int col0 = blockIdx.x * 128;

    const int ldRow = tid >> 1;         // 0..127
    const int ldCol = (tid & 1) * 4;    // 0 or 4
    const float* Aload = A + (size_t)(row0 + ldRow) * K + ldCol;
    const float* Wload = W + (size_t)(col0 + ldRow) * K + ldCol;

    const int tx = tid & 15;            // 0..15
    const int ty = tid >> 4;            // 0..15

    float acc[8][8];
#pragma unroll
    for (int i = 0; i < 8; i++)
#pragma unroll
        for (int j = 0; j < 8; j++) acc[i][j] = 0.0f;

    for (int k0 = 0; k0 < K; k0 += 8) {
        float4 av = *(const float4*)(Aload + k0);
        float4 wv = *(const float4*)(Wload + k0);
        __syncthreads();
        As[ldCol + 0][ldRow] = av.x;
        As[ldCol + 1][ldRow] = av.y;
        As[ldCol + 2][ldRow] = av.z;
        As[ldCol + 3][ldRow] = av.w;
        Bs[ldCol + 0][ldRow] = wv.x;
        Bs[ldCol + 1][ldRow] = wv.y;
        Bs[ldCol + 2][ldRow] = wv.z;
        Bs[ldCol + 3][ldRow] = wv.w;
        __syncthreads();

#pragma unroll
        for (int kk = 0; kk < 8; kk++) {
            float a[8], b[8];
            *(float4*)(a)     = *(const float4*)&As[kk][ty * 8];
            *(float4*)(a + 4) = *(const float4*)&As[kk][ty * 8 + 4];
            *(float4*)(b)     = *(const float4*)&Bs[kk][tx * 8];
            *(float4*)(b + 4) = *(const float4*)&Bs[kk][tx * 8 + 4];
#pragma unroll
            for (int i = 0; i < 8; i++)
#pragma unroll
                for (int j = 0; j < 8; j++)
                    acc[i][j] += a[i] * b[j];
        }
    }

#pragma unroll
    for (int i = 0; i < 8; i++) {
        const int rm = row0 + ty * 8 + i;
#pragma unroll
        for (int j = 0; j < 8; j += 4) {
            const int cn = col0 + tx * 8 + j;
            float4 o;
            o.x = acc[i][j]     + bias[cn];
            o.y = acc[i][j + 1] + bias[cn + 1];
            o.z = acc[i][j + 2] + bias[cn + 2];
            o.w = acc[i][j + 3] + bias[cn + 3];
            *(float4*)(C + (size_t)rm * N + cn) = o;
        }
    }
}

// ---------------------------------------------------------------------------
// Flash attention, fp32, one query row per thread. 64 threads per block.
// Block = (q-tile 64 rows, head, batch). Causal tile skipping.
// Masked scores are set to the literal -1e9 so the degenerate all-masked-row
// softmax (uniform over ALL keys) matches the reference; an explicit fallback
// covers that case exactly.
// ---------------------------------------------------------------------------
__global__ __launch_bounds__(64)
void flash_attn(const float* __restrict__ Q, const float* __restrict__ K,
                const float* __restrict__ V, float* __restrict__ O)
{
    __shared__ float Ks[64][64];
    __shared__ float Vs[64][64];
    __shared__ float padp[64];

    const int qt  = blockIdx.x;
    const int h   = blockIdx.y;
    const int b   = blockIdx.z;
    const int tid = threadIdx.x;
    const int qrow = qt * 64 + tid;
    const float scale = 0.125f;   // 1/sqrt(64)

    // q row -> registers
    float q[64];
    {
        const float* qptr = Q + ((size_t)(b * S_LEN + qrow) * DM + h * HD);
#pragma unroll
        for (int i = 0; i < 64; i += 4) {
            float4 v = *(const float4*)(qptr + i);
            q[i] = v.x; q[i + 1] = v.y; q[i + 2] = v.z; q[i + 3] = v.w;
        }
    }

    float m = -3.0e38f, l = 0.0f;
    float o[64];
#pragma unroll
    for (int i = 0; i < 64; i++) o[i] = 0.0f;

    const int ntiles = qt + 1;
    for (int kt = 0; kt < ntiles; kt++) {
        __syncthreads();
        {
            const float* kbase = K + ((size_t)(b * S_LEN + kt * 64) * DM + h * HD);
            const float* vbase = V + ((size_t)(b * S_LEN + kt * 64) * DM + h * HD);
#pragma unroll
            for (int it = 0; it < 16; it++) {
                int idx = it * 64 + tid;            // float4 index, 0..1023
                int r = idx >> 4;
                int cc = (idx & 15) * 4;
                *(float4*)&Ks[r][cc] = *(const float4*)(kbase + (size_t)r * DM + cc);
                *(float4*)&Vs[r][cc] = *(const float4*)(vbase + (size_t)r * DM + cc);
            }
            padp[tid] = g_pad[b * S_LEN + kt * 64 + tid];
        }
        __syncthreads();

        float s[64];
        const int kidx0 = kt * 64;
#pragma unroll
        for (int j = 0; j < 64; j++) {
            float d0 = 0.f, d1 = 0.f, d2 = 0.f, d3 = 0.f;
#pragma unroll
            for (int kk = 0; kk < 64; kk += 4) {
                float4 kv = *(const float4*)&Ks[j][kk];
                d0 += q[kk]     * kv.x;
                d1 += q[kk + 1] * kv.y;
                d2 += q[kk + 2] * kv.z;
                d3 += q[kk + 3] * kv.w;
            }
            float sc = ((d0 + d1) + (d2 + d3)) * scale;
            bool valid = (kidx0 + j <= qrow) && (padp[j] == 0.0f);
            s[j] = valid ? sc : -1.0e9f;
        }

        float tmax = s[0];
#pragma unroll
        for (int j = 1; j < 64; j++) tmax = fmaxf(tmax, s[j]);
        float mnew = fmaxf(m, tmax);
        float corr = __expf(m - mnew);
        l *= corr;
#pragma unroll
        for (int kk = 0; kk < 64; kk++) o[kk] *= corr;

#pragma unroll
        for (int j = 0; j < 64; j++) {
            float p = __expf(s[j] - mnew);
            l += p;
#pragma unroll
            for (int kk = 0; kk < 64; kk += 4) {
                float4 vv = *(const float4*)&Vs[j][kk];
                o[kk]     += p * vv.x;
                o[kk + 1] += p * vv.y;
                o[kk + 2] += p * vv.z;
                o[kk + 3] += p * vv.w;
            }
        }
        m = mnew;
    }

    // Degenerate case: entire causal prefix was padded -> reference softmax is
    // uniform over ALL S_LEN keys. Essentially never taken; exact when taken.
    if (m <= -9.9e8f) {
#pragma unroll
        for (int kk = 0; kk < 64; kk++) o[kk] = 0.0f;
        const float* vb = V + ((size_t)b * S_LEN) * DM + h * HD;
        for (int key = 0; key < S_LEN; key++) {
#pragma unroll
            for (int kk = 0; kk < 64; kk += 4) {
                float4 vv = *(const float4*)(vb + (size_t)key * DM + kk);
                o[kk] += vv.x; o[kk + 1] += vv.y; o[kk + 2] += vv.z; o[kk + 3] += vv.w;
            }
        }
        l = (float)S_LEN;
    }

    const float invl = 1.0f / l;
    float* optr = O + ((size_t)(b * S_LEN + qrow) * DM + h * HD);
#pragma unroll
    for (int kk = 0; kk < 64; kk += 4) {
        float4 w;
        w.x = o[kk] * invl; w.y = o[kk + 1] * invl;
        w.z = o[kk + 2] * invl; w.w = o[kk + 3] * invl;
        *(float4*)(optr + kk) = w;
    }
}

// ---------------------------------------------------------------------------
extern "C" void kernel_launch(void* const* d_in, const int* in_sizes, int n_in,
                              void* d_out, int out_size)
{
    const float* x   = (const float*)d_in[0];
    const int*   ids = (const int*)  d_in[1];   // int32 or int64; sniffed on device
    const float* Wq  = (const float*)d_in[2];
    const float* bq  = (const float*)d_in[3];
    const float* Wk  = (const float*)d_in[4];
    const float* bk  = (const float*)d_in[5];
    const float* Wv  = (const float*)d_in[6];
    const float* bv  = (const float*)d_in[7];
    const float* Wo  = (const float*)d_in[8];
    const float* bo  = (const float*)d_in[9];
    float* out = (float*)d_out;

    float *Qp, *Kp, *Vp, *Op;
    cudaGetSymbolAddress((void**)&Qp, g_Q);
    cudaGetSymbolAddress((void**)&Kp, g_K);
    cudaGetSymbolAddress((void**)&Vp, g_V);
    cudaGetSymbolAddress((void**)&Op, g_O);

    pad_kernel<<<1, 256>>>(ids);

    dim3 gg(DM / 128, M_TOT / 128);   // (8, 32)
    sgemm_tn<<<gg, 256>>>(x, Wq, bq, Qp, M_TOT, DM, DM);
    sgemm_tn<<<gg, 256>>>(x, Wk, bk, Kp, M_TOT, DM, DM);
    sgemm_tn<<<gg, 256>>>(x, Wv, bv, Vp, M_TOT, DM, DM);

    dim3 gf(S_LEN / 64, NH, BATCH);   // (32, 16, 2)
    flash_attn<<<gf, 64>>>(Qp, Kp, Vp, Op);

    sgemm_tn<<<gg, 256>>>(Op, Wo, bo, out, M_TOT, DM, DM);
}

// round 2
// speedup vs baseline: 3.3987x; 3.3987x over previous
#include <cuda_runtime.h>
#include <cstdint>

#define S_LEN 2048
#define DM    1024
#define NH    16
#define HD    64
#define BATCH 2
#define M_TOT (BATCH * S_LEN)   // 4096

// ---------------- scratch (device globals: no allocation allowed) ----------
__device__ float g_Q[M_TOT * DM];
__device__ float g_K[M_TOT * DM];
__device__ float g_V[M_TOT * DM];
__device__ float g_O[M_TOT * DM];
__device__ float g_pad[BATCH * S_LEN];   // 1.0f = padded (id==0), 0.0f = valid

// ---------------------------------------------------------------------------
__device__ __forceinline__ uint32_t f2tf(float f) {
    uint32_t u;
    asm("cvt.rna.tf32.f32 %0, %1;" : "=r"(u) : "f"(f));
    return u;
}

__device__ __forceinline__ void mma8(float* c, const uint32_t* a, const uint32_t* b) {
    asm volatile(
        "mma.sync.aligned.m16n8k8.row.col.f32.tf32.tf32.f32 "
        "{%0,%1,%2,%3},{%4,%5,%6,%7},{%8,%9},{%0,%1,%2,%3};"
        : "+f"(c[0]), "+f"(c[1]), "+f"(c[2]), "+f"(c[3])
        : "r"(a[0]), "r"(a[1]), "r"(a[2]), "r"(a[3]), "r"(b[0]), "r"(b[1]));
}

// ---------------------------------------------------------------------------
// Pad-flag kernel with int32/int64 dtype sniffing (see R0 notes).
// ---------------------------------------------------------------------------
__global__ void pad_kernel(const int* __restrict__ ids)
{
    __shared__ int orv;
    if (threadIdx.x == 0) orv = 0;
    __syncthreads();
    int local = 0;
    for (int i = threadIdx.x; i < 2048; i += blockDim.x)
        local |= ids[2 * i + 1];
    atomicOr(&orv, local);
    __syncthreads();
    bool is64 = (orv == 0);
    for (int i = threadIdx.x; i < BATCH * S_LEN; i += blockDim.x) {
        int nz = is64 ? ((ids[2 * i] | ids[2 * i + 1]) != 0) : (ids[i] != 0);
        g_pad[i] = nz ? 0.0f : 1.0f;
    }
}

// ---------------------------------------------------------------------------
// TF32 tensor-core GEMM (NT): C[m][n] = sum_k A[m][k]*W[n][k] + bias[n]
// 128x128 tile, BK=16, 8 warps (64x32 warp tiles), m16n8k8 tf32 mma.
// ---------------------------------------------------------------------------
__global__ __launch_bounds__(256)
void gemm_tf32(const float* __restrict__ A, const float* __restrict__ W,
               const float* __restrict__ bias, float* __restrict__ C,
               int M, int N, int K)
{
    __shared__ uint32_t As[16][136];   // [k][m], stride 136 -> bank = 8k+m
    __shared__ uint32_t Bs[16][136];   // [k][n]

    const int tid  = threadIdx.x;
    const int lane = tid & 31;
    const int wid  = tid >> 5;
    const int g    = lane >> 2;   // 0..7
    const int t    = lane & 3;    // 0..3
    const int warp_m = wid & 1;   // 0..1 (64 rows each)
    const int warp_n = wid >> 1;  // 0..3 (32 cols each)

    const int row0 = blockIdx.y * 128;
    const int col0 = blockIdx.x * 128;

    // loader mapping: conflict-free STS, same-kq within warp
    int lr[2], lkq[2];
#pragma unroll
    for (int it = 0; it < 2; it++) {
        int linear = it * 256 + tid;
        lr[it]  = (linear & 31) | ((linear >> 7) << 5);
        lkq[it] = ((linear >> 5) & 3) * 4;
    }
    const float* Ap[2] = { A + (size_t)(row0 + lr[0]) * K + lkq[0],
                           A + (size_t)(row0 + lr[1]) * K + lkq[1] };
    const float* Wp[2] = { W + (size_t)(col0 + lr[0]) * K + lkq[0],
                           W + (size_t)(col0 + lr[1]) * K + lkq[1] };

    float c[4][4][4];
#pragma unroll
    for (int i = 0; i < 4; i++)
#pragma unroll
        for (int j = 0; j < 4; j++)
#pragma unroll
            for (int q = 0; q < 4; q++) c[i][j][q] = 0.0f;

    float4 pa[2], pb[2];
#pragma unroll
    for (int it = 0; it < 2; it++) {
        pa[it] = *(const float4*)(Ap[it]);
        pb[it] = *(const float4*)(Wp[it]);
    }

    for (int k0 = 0; k0 < K; k0 += 16) {
        __syncthreads();
#pragma unroll
        for (int it = 0; it < 2; it++) {
            As[lkq[it] + 0][lr[it]] = f2tf(pa[it].x);
            As[lkq[it] + 1][lr[it]] = f2tf(pa[it].y);
            As[lkq[it] + 2][lr[it]] = f2tf(pa[it].z);
            As[lkq[it] + 3][lr[it]] = f2tf(pa[it].w);
            Bs[lkq[it] + 0][lr[it]] = f2tf(pb[it].x);
            Bs[lkq[it] + 1][lr[it]] = f2tf(pb[it].y);
            Bs[lkq[it] + 2][lr[it]] = f2tf(pb[it].z);
            Bs[lkq[it] + 3][lr[it]] = f2tf(pb[it].w);
        }
        __syncthreads();
        if (k0 + 16 < K) {
#pragma unroll
            for (int it = 0; it < 2; it++) {
                pa[it] = *(const float4*)(Ap[it] + k0 + 16);
                pb[it] = *(const float4*)(Wp[it] + k0 + 16);
            }
        }
#pragma unroll
        for (int ks = 0; ks < 16; ks += 8) {
            uint32_t af[4][4], bf[4][2];
#pragma unroll
            for (int i = 0; i < 4; i++) {
                int m = warp_m * 64 + i * 16 + g;
                af[i][0] = As[ks + t][m];
                af[i][1] = As[ks + t][m + 8];
                af[i][2] = As[ks + t + 4][m];
                af[i][3] = As[ks + t + 4][m + 8];
            }
#pragma unroll
            for (int j = 0; j < 4; j++) {
                int n = warp_n * 32 + j * 8 + g;
                bf[j][0] = Bs[ks + t][n];
                bf[j][1] = Bs[ks + t + 4][n];
            }
#pragma unroll
            for (int i = 0; i < 4; i++)
#pragma unroll
                for (int j = 0; j < 4; j++)
                    mma8(c[i][j], af[i], bf[j]);
        }
    }

#pragma unroll
    for (int i = 0; i < 4; i++) {
        int rm = row0 + warp_m * 64 + i * 16 + g;
#pragma unroll
        for (int j = 0; j < 4; j++) {
            int cn = col0 + warp_n * 32 + j * 8 + 2 * t;
            float b0 = bias[cn], b1 = bias[cn + 1];
            float2 v0 = make_float2(c[i][j][0] + b0, c[i][j][1] + b1);
            float2 v1 = make_float2(c[i][j][2] + b0, c[i][j][3] + b1);
            *(float2*)&C[(size_t)rm * N + cn]       = v0;
            *(float2*)&C[(size_t)(rm + 8) * N + cn] = v1;
        }
    }
}

// ---------------------------------------------------------------------------
// Flash attention v2 on tf32 tensor cores.
// Block: 128 threads (4 warps), 64-query tile; warp owns 16 rows.
// K stored transposed [d][key] (stride 72), V [key][d] (stride 72), both tf32.
// P round-trips through smem (aliases K region) as tf32 a-fragments.
// ---------------------------------------------------------------------------
#define FLD 72

__global__ __launch_bounds__(128)
void flash_tc(const float* __restrict__ Q, const float* __restrict__ K,
              const float* __restrict__ V, float* __restrict__ O)
{
    __shared__ uint32_t sKP[64 * FLD];   // Ks[d][key] tf32, later Ps[row][key] tf32
    __shared__ uint32_t sV[64 * FLD];    // Vs[key][d] tf32
    __shared__ float    sPad[64];

    const int qt  = gridDim.x - 1 - blockIdx.x;   // biggest blocks first
    const int h   = blockIdx.y;
    const int bb  = blockIdx.z;
    const int tid = threadIdx.x;
    const int lane = tid & 31;
    const int w    = tid >> 5;   // warp 0..3
    const int g    = lane >> 2;  // 0..7
    const int t    = lane & 3;   // 0..3
    const int hoff = h * HD;

    const int qlow  = qt * 64 + w * 16 + g;
    const int qhigh = qlow + 8;
    const size_t qrowbase = (size_t)(bb * S_LEN + qt * 64 + w * 16);

    // Q fragments (scaled by 1/8 = exact in tf32), register resident.
    uint32_t aQ[8][4];
#pragma unroll
    for (int kd = 0; kd < 8; kd++) {
        int cq = hoff + kd * 8 + t;
        aQ[kd][0] = f2tf(Q[(qrowbase + g) * DM + cq] * 0.125f);
        aQ[kd][1] = f2tf(Q[(qrowbase + g + 8) * DM + cq] * 0.125f);
        aQ[kd][2] = f2tf(Q[(qrowbase + g) * DM + cq + 4] * 0.125f);
        aQ[kd][3] = f2tf(Q[(qrowbase + g + 8) * DM + cq + 4] * 0.125f);
    }

    float m0 = -3.0e38f, m1 = -3.0e38f, l0 = 0.0f, l1 = 0.0f;
    float cO[8][4];
#pragma unroll
    for (int j = 0; j < 8; j++)
#pragma unroll
        for (int q = 0; q < 4; q++) cO[j][q] = 0.0f;

    const int ntiles = qt + 1;
    for (int kt = 0; kt < ntiles; kt++) {
        const int kbase = bb * S_LEN + kt * 64;
        __syncthreads();   // prior tile fully consumed
        // K tile: Ks[d][key] (transposed, tf32)
#pragma unroll
        for (int it = 0; it < 8; it++) {
            int linear = it * 128 + tid;
            int key = linear & 63;
            int dq  = linear >> 6;   // 0..15
            float4 kv = *(const float4*)&K[(size_t)(kbase + key) * DM + hoff + dq * 4];
            sKP[(dq * 4 + 0) * FLD + key] = f2tf(kv.x);
            sKP[(dq * 4 + 1) * FLD + key] = f2tf(kv.y);
            sKP[(dq * 4 + 2) * FLD + key] = f2tf(kv.z);
            sKP[(dq * 4 + 3) * FLD + key] = f2tf(kv.w);
        }
        // V tile: Vs[key][d] (tf32)
#pragma unroll
        for (int it = 0; it < 8; it++) {
            int linear = it * 128 + tid;
            int key = linear >> 4;    // 0..63
            int dq  = linear & 15;
            float4 vv = *(const float4*)&V[(size_t)(kbase + key) * DM + hoff + dq * 4];
            sV[key * FLD + dq * 4 + 0] = f2tf(vv.x);
            sV[key * FLD + dq * 4 + 1] = f2tf(vv.y);
            sV[key * FLD + dq * 4 + 2] = f2tf(vv.z);
            sV[key * FLD + dq * 4 + 3] = f2tf(vv.w);
        }
        if (tid < 64) sPad[tid] = g_pad[kbase + tid];
        __syncthreads();

        // S = (Q/8) K^T : 16x64 per warp in 8 n-fragments
        float cS[8][4];
#pragma unroll
        for (int jn = 0; jn < 8; jn++) {
            cS[jn][0] = cS[jn][1] = cS[jn][2] = cS[jn][3] = 0.0f;
#pragma unroll
            for (int kd = 0; kd < 8; kd++) {
                uint32_t bK[2];
                bK[0] = sKP[(kd * 8 + t) * FLD + jn * 8 + g];
                bK[1] = sKP[(kd * 8 + t + 4) * FLD + jn * 8 + g];
                mma8(cS[jn], aQ[kd], bK);
            }
        }

        // mask (causal + pad); masked -> exactly -1e9
        float mx0 = -3.0e38f, mx1 = -3.0e38f;
#pragma unroll
        for (int jn = 0; jn < 8; jn++) {
            int col = jn * 8 + 2 * t;
            int k0g = kt * 64 + col;
            bool p0 = (sPad[col] == 0.0f);
            bool p1 = (sPad[col + 1] == 0.0f);
            cS[jn][0] = (k0g     <= qlow  && p0) ? cS[jn][0] : -1.0e9f;
            cS[jn][1] = (k0g + 1 <= qlow  && p1) ? cS[jn][1] : -1.0e9f;
            cS[jn][2] = (k0g     <= qhigh && p0) ? cS[jn][2] : -1.0e9f;
            cS[jn][3] = (k0g + 1 <= qhigh && p1) ? cS[jn][3] : -1.0e9f;
            mx0 = fmaxf(mx0, fmaxf(cS[jn][0], cS[jn][1]));
            mx1 = fmaxf(mx1, fmaxf(cS[jn][2], cS[jn][3]));
        }
        mx0 = fmaxf(mx0, __shfl_xor_sync(0xffffffffu, mx0, 1));
        mx0 = fmaxf(mx0, __shfl_xor_sync(0xffffffffu, mx0, 2));
        mx1 = fmaxf(mx1, __shfl_xor_sync(0xffffffffu, mx1, 1));
        mx1 = fmaxf(mx1, __shfl_xor_sync(0xffffffffu, mx1, 2));

        float mn0 = fmaxf(m0, mx0), mn1 = fmaxf(m1, mx1);
        float cor0 = __expf(m0 - mn0), cor1 = __expf(m1 - mn1);

        float rs0 = 0.0f, rs1 = 0.0f;
#pragma unroll
        for (int jn = 0; jn < 8; jn++) {
            cS[jn][0] = __expf(cS[jn][0] - mn0);
            cS[jn][1] = __expf(cS[jn][1] - mn0);
            cS[jn][2] = __expf(cS[jn][2] - mn1);
            cS[jn][3] = __expf(cS[jn][3] - mn1);
            rs0 += cS[jn][0] + cS[jn][1];
            rs1 += cS[jn][2] + cS[jn][3];
            cO[jn][0] *= cor0; cO[jn][1] *= cor0;
            cO[jn][2] *= cor1; cO[jn][3] *= cor1;
        }
        rs0 += __shfl_xor_sync(0xffffffffu, rs0, 1);
        rs0 += __shfl_xor_sync(0xffffffffu, rs0, 2);
        rs1 += __shfl_xor_sync(0xffffffffu, rs1, 1);
        rs1 += __shfl_xor_sync(0xffffffffu, rs1, 2);
        l0 = l0 * cor0 + rs0;
        l1 = l1 * cor1 + rs1;
        m0 = mn0; m1 = mn1;

        __syncthreads();   // all warps done reading Ks before Ps overwrites it

        // P -> smem (tf32 a-operand layout: Ps[row][key], stride FLD)
        {
            int pr0 = (w * 16 + g) * FLD;
            int pr1 = (w * 16 + g + 8) * FLD;
#pragma unroll
            for (int jn = 0; jn < 8; jn++) {
                int pc = jn * 8 + 2 * t;
                sKP[pr0 + pc]     = f2tf(cS[jn][0]);
                sKP[pr0 + pc + 1] = f2tf(cS[jn][1]);
                sKP[pr1 + pc]     = f2tf(cS[jn][2]);
                sKP[pr1 + pc + 1] = f2tf(cS[jn][3]);
            }
        }
        __syncwarp();

        // O += P V
        {
            int pr0 = (w * 16 + g) * FLD;
            int pr1 = (w * 16 + g + 8) * FLD;
#pragma unroll
            for (int kd = 0; kd < 8; kd++) {
                uint32_t aP[4];
                aP[0] = sKP[pr0 + kd * 8 + t];
                aP[1] = sKP[pr1 + kd * 8 + t];
                aP[2] = sKP[pr0 + kd * 8 + t + 4];
                aP[3] = sKP[pr1 + kd * 8 + t + 4];
#pragma unroll
                for (int jn = 0; jn < 8; jn++) {
                    uint32_t bV[2];
                    bV[0] = sV[(kd * 8 + t) * FLD + jn * 8 + g];
                    bV[1] = sV[(kd * 8 + t + 4) * FLD + jn * 8 + g];
                    mma8(cO[jn], aP, bV);
                }
            }
        }
    }

    // Degenerate rows (entire causal prefix padded): reference softmax is
    // uniform over ALL S_LEN keys. Essentially never taken; exact when taken.
    if (m0 <= -9.9e8f) {
        l0 = (float)S_LEN;
#pragma unroll
        for (int jn = 0; jn < 8; jn++) {
            int d0 = hoff + jn * 8 + 2 * t;
            float s0 = 0.0f, s1 = 0.0f;
            for (int key = 0; key < S_LEN; key++) {
                const float* vp = V + (size_t)(bb * S_LEN + key) * DM + d0;
                s0 += vp[0]; s1 += vp[1];
            }
            cO[jn][0] = s0; cO[jn][1] = s1;
        }
    }
    if (m1 <= -9.9e8f) {
        l1 = (float)S_LEN;
#pragma unroll
        for (int jn = 0; jn < 8; jn++) {
            int d0 = hoff + jn * 8 + 2 * t;
            float s0 = 0.0f, s1 = 0.0f;
            for (int key = 0; key < S_LEN; key++) {
                const float* vp = V + (size_t)(bb * S_LEN + key) * DM + d0;
                s0 += vp[0]; s1 += vp[1];
            }
            cO[jn][2] = s0; cO[jn][3] = s1;
        }
    }

    const float il0 = 1.0f / l0, il1 = 1.0f / l1;
    const size_t or0 = (qrowbase + g) * DM + hoff;
    const size_t or1 = (qrowbase + g + 8) * DM + hoff;
#pragma unroll
    for (int jn = 0; jn < 8; jn++) {
        int dc = jn * 8 + 2 * t;
        *(float2*)&O[or0 + dc] = make_float2(cO[jn][0] * il0, cO[jn][1] * il0);
        *(float2*)&O[or1 + dc] = make_float2(cO[jn][2] * il1, cO[jn][3] * il1);
    }
}

// ---------------------------------------------------------------------------
extern "C" void kernel_launch(void* const* d_in, const int* in_sizes, int n_in,
                              void* d_out, int out_size)
{
    const float* x   = (const float*)d_in[0];
    const int*   ids = (const int*)  d_in[1];
    const float* Wq  = (const float*)d_in[2];
    const float* bq  = (const float*)d_in[3];
    const float* Wk  = (const float*)d_in[4];
    const float* bk  = (const float*)d_in[5];
    const float* Wv  = (const float*)d_in[6];
    const float* bv  = (const float*)d_in[7];
    const float* Wo  = (const float*)d_in[8];
    const float* bo  = (const float*)d_in[9];
    float* out = (float*)d_out;

    float *Qp, *Kp, *Vp, *Op;
    cudaGetSymbolAddress((void**)&Qp, g_Q);
    cudaGetSymbolAddress((void**)&Kp, g_K);
    cudaGetSymbolAddress((void**)&Vp, g_V);
    cudaGetSymbolAddress((void**)&Op, g_O);

    pad_kernel<<<1, 256>>>(ids);

    dim3 gg(DM / 128, M_TOT / 128);   // (8, 32)
    gemm_tf32<<<gg, 256>>>(x, Wq, bq, Qp, M_TOT, DM, DM);
    gemm_tf32<<<gg, 256>>>(x, Wk, bk, Kp, M_TOT, DM, DM);
    gemm_tf32<<<gg, 256>>>(x, Wv, bv, Vp, M_TOT, DM, DM);

    dim3 gf(S_LEN / 64, NH, BATCH);   // (32, 16, 2)
    flash_tc<<<gf, 128>>>(Qp, Kp, Vp, Op);

    gemm_tf32<<<gg, 256>>>(Op, Wo, bo, out, M_TOT, DM, DM);
}